// round 5
// baseline (speedup 1.0000x reference)
#include <cuda_runtime.h>
#include <cuda_fp16.h>
#include <math.h>

#define NN      50000
#define EE      1600000
#define FIN     256
#define H       4
#define D       32
#define HD      128
#define C       16
#define NBLK    196     // ceil(NN/256)

// ---------------- scratch ------------------------------------------------
__device__ __align__(16) __half g_feat1h[NN * HD];   // fp16 gather copy (sole feat1 storage)
__device__ __align__(16) float g_el1[NN * H];
__device__ __align__(16) float g_er1[NN * H];
__device__ __align__(16) float g_h[NN * HD];
__device__ __align__(16) __half g_feat2h[NN * C];
__device__ __align__(16) float g_el2[NN];
__device__ __align__(16) float g_er2[NN];
// CSR build
__device__ int g_cnt[NN];
__device__ int g_off[NN + 1];
__device__ int g_cur[NN];
__device__ int g_ebuf[EE];     // src node id, sorted by dst
__device__ int g_bsum[NBLK];
__device__ int g_bpre[NBLK + 1];

__device__ __forceinline__ float lrelu(float v) { return v > 0.f ? v : 0.2f * v; }
__device__ __forceinline__ float elu1(float v)  { return v > 0.f ? v : (__expf(v) - 1.f); }

// ---------------- CSR build ---------------------------------------------
__global__ void k_zero_cnt() {
    int i = blockIdx.x * blockDim.x + threadIdx.x;
    if (i < NN) g_cnt[i] = 0;
}

__global__ void k_hist(const int* __restrict__ dst, int e_cnt) {
    int e = blockIdx.x * blockDim.x + threadIdx.x;
    if (e < e_cnt) atomicAdd(&g_cnt[dst[e]], 1);
}

__global__ void k_scan1() {
    __shared__ int sh[256];
    int t = threadIdx.x;
    int i = blockIdx.x * 256 + t;
    int v = (i < NN) ? g_cnt[i] : 0;
    sh[t] = v;
    __syncthreads();
#pragma unroll
    for (int ofs = 1; ofs < 256; ofs <<= 1) {
        int x = (t >= ofs) ? sh[t - ofs] : 0;
        __syncthreads();
        sh[t] += x;
        __syncthreads();
    }
    if (i < NN) g_off[i] = sh[t] - v;           // exclusive
    if (t == 255) g_bsum[blockIdx.x] = sh[255];
}

__global__ void k_scan2() {
    __shared__ int sh[256];
    int t = threadIdx.x;
    int v = (t < NBLK) ? g_bsum[t] : 0;
    sh[t] = v;
    __syncthreads();
#pragma unroll
    for (int ofs = 1; ofs < 256; ofs <<= 1) {
        int x = (t >= ofs) ? sh[t - ofs] : 0;
        __syncthreads();
        sh[t] += x;
        __syncthreads();
    }
    if (t < NBLK) g_bpre[t] = sh[t] - v;        // exclusive
}

__global__ void k_scan3(int e_cnt) {
    int i = blockIdx.x * blockDim.x + threadIdx.x;
    if (i < NN) {
        int o = g_off[i] + g_bpre[i >> 8];
        g_off[i] = o;
        g_cur[i] = o;
    }
    if (i == 0) g_off[NN] = e_cnt;
}

__global__ void k_scatter(const int* __restrict__ src, const int* __restrict__ dst, int e_cnt) {
    int e = blockIdx.x * blockDim.x + threadIdx.x;
    if (e >= e_cnt) return;
    int pos = atomicAdd(&g_cur[dst[e]], 1);
    g_ebuf[pos] = src[e];
}

// ---------------- K1: feat1 = x @ W1, fused el/er + fp16 store ----------
__global__ __launch_bounds__(256) void k_gemm1(const float* __restrict__ x,
                                               const float* __restrict__ W1,
                                               const float* __restrict__ al1,
                                               const float* __restrict__ ar1,
                                               int n) {
    __shared__ float xs[64][32];
    __shared__ float ws[32][128];
    int t = threadIdx.x;
    int lane = t & 31;
    int row0 = blockIdx.x * 64;
    int c0 = lane * 4;
    int r0 = (t >> 5) * 8;
    float acc[8][4];
#pragma unroll
    for (int i = 0; i < 8; i++) { acc[i][0]=0.f; acc[i][1]=0.f; acc[i][2]=0.f; acc[i][3]=0.f; }

    for (int k0 = 0; k0 < FIN; k0 += 32) {
        {
            int rl = t >> 3;
            int kc = (t & 7) * 4;
#pragma unroll
            for (int i = 0; i < 2; i++) {
                int r = rl + i * 32;
                int gr = row0 + r;
                float4 v = make_float4(0.f, 0.f, 0.f, 0.f);
                if (gr < n) v = *(const float4*)&x[(long)gr * FIN + k0 + kc];
                *(float4*)&xs[r][kc] = v;
            }
        }
        {
            int kl = t >> 5;
#pragma unroll
            for (int i = 0; i < 4; i++) {
                int kr = kl + i * 8;
                *(float4*)&ws[kr][c0] = *(const float4*)&W1[(k0 + kr) * HD + c0];
            }
        }
        __syncthreads();
#pragma unroll
        for (int k = 0; k < 32; k++) {
            float4 w4 = *(float4*)&ws[k][c0];
#pragma unroll
            for (int i = 0; i < 8; i++) {
                float xv = xs[r0 + i][k];
                acc[i][0] += xv * w4.x;
                acc[i][1] += xv * w4.y;
                acc[i][2] += xv * w4.z;
                acc[i][3] += xv * w4.w;
            }
        }
        __syncthreads();
    }

    float4 al4 = *(const float4*)&al1[c0];
    float4 ar4 = *(const float4*)&ar1[c0];
    int head = lane >> 3;
#pragma unroll
    for (int i = 0; i < 8; i++) {
        int gr = row0 + r0 + i;
        float elp = acc[i][0]*al4.x + acc[i][1]*al4.y + acc[i][2]*al4.z + acc[i][3]*al4.w;
        float erp = acc[i][0]*ar4.x + acc[i][1]*ar4.y + acc[i][2]*ar4.z + acc[i][3]*ar4.w;
#pragma unroll
        for (int m = 1; m < 8; m <<= 1) {
            elp += __shfl_xor_sync(0xffffffffu, elp, m);
            erp += __shfl_xor_sync(0xffffffffu, erp, m);
        }
        if (gr < n) {
            __half2 h01 = __floats2half2_rn(acc[i][0], acc[i][1]);
            __half2 h23 = __floats2half2_rn(acc[i][2], acc[i][3]);
            uint2 packed = make_uint2(*(unsigned*)&h01, *(unsigned*)&h23);
            *(uint2*)&g_feat1h[(long)gr * HD + c0] = packed;
            if ((lane & 7) == 0) {
                g_el1[gr * 4 + head] = elp;
                g_er1[gr * 4 + head] = erp;
            }
        }
    }
}

// ---------------- K2: fused layer-1 attention + aggregation + act -------
// one warp per dst node; lane owns 4 consecutive feats (one head per 8 lanes)
__global__ __launch_bounds__(256) void k_layer1(const float* __restrict__ b1, int n) {
    int wid = (blockIdx.x * blockDim.x + threadIdx.x) >> 5;
    if (wid >= n) return;
    int lane = threadIdx.x & 31;
    int head = lane >> 3;
    int d = wid;
    int off0 = g_off[d], off1 = g_off[d + 1];
    float er = g_er1[d * 4 + head];
    float ax = 0.f, ay = 0.f, az = 0.f, aw = 0.f, wsum = 0.f;

    int j = off0;
    int s = (j < off1) ? __ldg(&g_ebuf[j]) : 0;
    while (j < off1) {
        int s_next = (j + 1 < off1) ? __ldg(&g_ebuf[j + 1]) : 0;
        float el = __ldg(&g_el1[s * 4 + head]);
        uint2 p = *(const uint2*)&g_feat1h[(long)s * HD + lane * 4];
        float2 f01 = __half22float2(*(__half2*)&p.x);
        float2 f23 = __half22float2(*(__half2*)&p.y);
        float w = __expf(lrelu(el + er));
        ax += f01.x * w; ay += f01.y * w; az += f23.x * w; aw += f23.y * w;
        wsum += w;
        s = s_next;
        j++;
    }
    float inv = 1.f / fmaxf(wsum, 1e-9f);
    float4 b = *(const float4*)&b1[lane * 4];
    float4 o;
    o.x = elu1(ax * inv + b.x);
    o.y = elu1(ay * inv + b.y);
    o.z = elu1(az * inv + b.z);
    o.w = elu1(aw * inv + b.w);
    *(float4*)&g_h[(long)d * HD + lane * 4] = o;
}

// ---------------- K3: feat2 = h @ W2 [N,128]x[128,16] + el2/er2 ---------
__global__ __launch_bounds__(256) void k_gemm2(const float* __restrict__ W2,
                                               const float* __restrict__ al2,
                                               const float* __restrict__ ar2, int n) {
    __shared__ float w2s[HD * C];
    __shared__ float al2s[C], ar2s[C];
    int t = threadIdx.x;
    for (int j = t; j < HD * C; j += 256) w2s[j] = W2[j];
    if (t < C) { al2s[t] = al2[t]; ar2s[t] = ar2[t]; }
    __syncthreads();
    int node = blockIdx.x * 256 + t;
    if (node >= n) return;
    float acc[C];
#pragma unroll
    for (int c = 0; c < C; c++) acc[c] = 0.f;
    const float* hr = &g_h[(long)node * HD];
#pragma unroll 4
    for (int kk = 0; kk < 32; kk++) {
        float4 f = *(const float4*)&hr[kk * 4];
        const float* wrow = &w2s[(kk * 4) * C];
#pragma unroll
        for (int c = 0; c < C; c++) {
            acc[c] += f.x * wrow[c] + f.y * wrow[C + c] + f.z * wrow[2 * C + c] + f.w * wrow[3 * C + c];
        }
    }
    float el = 0.f, er = 0.f;
#pragma unroll
    for (int c = 0; c < C; c++) { el += acc[c] * al2s[c]; er += acc[c] * ar2s[c]; }
    __half* out = &g_feat2h[(long)node * C];
#pragma unroll
    for (int c2 = 0; c2 < 8; c2++) {
        __half2 hv = __floats2half2_rn(acc[c2 * 2], acc[c2 * 2 + 1]);
        *(__half2*)&out[c2 * 2] = hv;
    }
    g_el2[node] = el;
    g_er2[node] = er;
}

// ---------------- K4: fused layer-2 attention + aggregation + output ----
// 16 threads per dst node (one per class)
__global__ __launch_bounds__(256) void k_layer2(const float* __restrict__ b2,
                                                float* __restrict__ out, int n) {
    int t = threadIdx.x;
    int d = blockIdx.x * 16 + (t >> 4);
    if (d >= n) return;
    int c = t & 15;
    int off0 = g_off[d], off1 = g_off[d + 1];
    float er = g_er2[d];
    float acc = 0.f, wsum = 0.f;

    int j = off0;
    int s = (j < off1) ? __ldg(&g_ebuf[j]) : 0;
    while (j < off1) {
        int s_next = (j + 1 < off1) ? __ldg(&g_ebuf[j + 1]) : 0;
        float el = __ldg(&g_el2[s]);
        float f = __half2float(g_feat2h[(long)s * C + c]);
        float w = __expf(lrelu(el + er));
        acc += f * w;
        wsum += w;
        s = s_next;
        j++;
    }
    out[(long)d * C + c] = acc / fmaxf(wsum, 1e-9f) + __ldg(&b2[c]);
}

extern "C" void kernel_launch(void* const* d_in, const int* in_sizes, int n_in,
                              void* d_out, int out_size) {
    const float* x   = (const float*)d_in[0];
    const int*   src = (const int*)d_in[1];
    const int*   dst = (const int*)d_in[2];
    const float* W1  = (const float*)d_in[3];
    const float* b1  = (const float*)d_in[4];
    const float* al1 = (const float*)d_in[5];
    const float* ar1 = (const float*)d_in[6];
    const float* W2  = (const float*)d_in[7];
    const float* b2  = (const float*)d_in[8];
    const float* al2 = (const float*)d_in[9];
    const float* ar2 = (const float*)d_in[10];
    float* out = (float*)d_out;

    int n = in_sizes[0] / FIN;   // 50000
    int e = in_sizes[1];         // 1600000
    int eb = (e + 255) / 256;

    k_zero_cnt<<<NBLK, 256>>>();
    k_gemm1<<<(n + 63) / 64, 256>>>(x, W1, al1, ar1, n);
    k_hist<<<eb, 256>>>(dst, e);
    k_scan1<<<NBLK, 256>>>();
    k_scan2<<<1, 256>>>();
    k_scan3<<<NBLK, 256>>>(e);
    k_scatter<<<eb, 256>>>(src, dst, e);

    k_layer1<<<(n * 32 + 255) / 256, 256>>>(b1, n);
    k_gemm2<<<(n + 255) / 256, 256>>>(W2, al2, ar2, n);
    k_layer2<<<(n * 16 + 255) / 256, 256>>>(b2, out, n);
}

// round 6
// speedup vs baseline: 1.0748x; 1.0748x over previous
#include <cuda_runtime.h>
#include <cuda_fp16.h>
#include <math.h>

#define NN      50000
#define EE      1600000
#define FIN     256
#define H       4
#define D       32
#define HD      128
#define C       16
#define NBLK    196     // ceil(NN/256)

// ---------------- scratch ------------------------------------------------
__device__ __align__(16) __half g_feat1h[NN * HD];
__device__ __align__(16) float g_el1[NN * H];
__device__ __align__(16) float g_er1[NN * H];
__device__ __align__(16) float g_h[NN * HD];
__device__ __align__(16) __half g_feat2h[NN * C];
__device__ __align__(16) float g_el2[NN];
__device__ __align__(16) float g_er2[NN];
// CSR build
__device__ int g_cnt[NN];
__device__ int g_off[NN + 1];
__device__ int g_cur[NN];
__device__ int g_ebuf[EE];
__device__ int g_bsum[NBLK];
__device__ int g_bpre[NBLK + 1];

__device__ __forceinline__ float lrelu(float v) { return v > 0.f ? v : 0.2f * v; }
__device__ __forceinline__ float elu1(float v)  { return v > 0.f ? v : (__expf(v) - 1.f); }

// ---------------- CSR build ---------------------------------------------
__global__ void k_zero_cnt() {
    int i = blockIdx.x * blockDim.x + threadIdx.x;
    if (i < NN) g_cnt[i] = 0;
}

__global__ void k_hist(const int* __restrict__ dst, int e_cnt) {
    int e = blockIdx.x * blockDim.x + threadIdx.x;
    if (e < e_cnt) atomicAdd(&g_cnt[dst[e]], 1);
}

__global__ void k_scan1() {
    __shared__ int sh[256];
    int t = threadIdx.x;
    int i = blockIdx.x * 256 + t;
    int v = (i < NN) ? g_cnt[i] : 0;
    sh[t] = v;
    __syncthreads();
#pragma unroll
    for (int ofs = 1; ofs < 256; ofs <<= 1) {
        int x = (t >= ofs) ? sh[t - ofs] : 0;
        __syncthreads();
        sh[t] += x;
        __syncthreads();
    }
    if (i < NN) g_off[i] = sh[t] - v;
    if (t == 255) g_bsum[blockIdx.x] = sh[255];
}

__global__ void k_scan2() {
    __shared__ int sh[256];
    int t = threadIdx.x;
    int v = (t < NBLK) ? g_bsum[t] : 0;
    sh[t] = v;
    __syncthreads();
#pragma unroll
    for (int ofs = 1; ofs < 256; ofs <<= 1) {
        int x = (t >= ofs) ? sh[t - ofs] : 0;
        __syncthreads();
        sh[t] += x;
        __syncthreads();
    }
    if (t < NBLK) g_bpre[t] = sh[t] - v;
}

__global__ void k_scan3(int e_cnt) {
    int i = blockIdx.x * blockDim.x + threadIdx.x;
    if (i < NN) {
        int o = g_off[i] + g_bpre[i >> 8];
        g_off[i] = o;
        g_cur[i] = o;
    }
    if (i == 0) g_off[NN] = e_cnt;
}

__global__ void k_scatter(const int* __restrict__ src, const int* __restrict__ dst, int e_cnt) {
    int e = blockIdx.x * blockDim.x + threadIdx.x;
    if (e >= e_cnt) return;
    int pos = atomicAdd(&g_cur[dst[e]], 1);
    g_ebuf[pos] = src[e];
}

// ---------------- K1: feat1 = x @ W1, fused el/er + fp16 store ----------
__global__ __launch_bounds__(256) void k_gemm1(const float* __restrict__ x,
                                               const float* __restrict__ W1,
                                               const float* __restrict__ al1,
                                               const float* __restrict__ ar1,
                                               int n) {
    __shared__ float xs[64][32];
    __shared__ float ws[32][128];
    int t = threadIdx.x;
    int lane = t & 31;
    int row0 = blockIdx.x * 64;
    int c0 = lane * 4;
    int r0 = (t >> 5) * 8;
    float acc[8][4];
#pragma unroll
    for (int i = 0; i < 8; i++) { acc[i][0]=0.f; acc[i][1]=0.f; acc[i][2]=0.f; acc[i][3]=0.f; }

    for (int k0 = 0; k0 < FIN; k0 += 32) {
        {
            int rl = t >> 3;
            int kc = (t & 7) * 4;
#pragma unroll
            for (int i = 0; i < 2; i++) {
                int r = rl + i * 32;
                int gr = row0 + r;
                float4 v = make_float4(0.f, 0.f, 0.f, 0.f);
                if (gr < n) v = *(const float4*)&x[(long)gr * FIN + k0 + kc];
                *(float4*)&xs[r][kc] = v;
            }
        }
        {
            int kl = t >> 5;
#pragma unroll
            for (int i = 0; i < 4; i++) {
                int kr = kl + i * 8;
                *(float4*)&ws[kr][c0] = *(const float4*)&W1[(k0 + kr) * HD + c0];
            }
        }
        __syncthreads();
#pragma unroll
        for (int k = 0; k < 32; k++) {
            float4 w4 = *(float4*)&ws[k][c0];
#pragma unroll
            for (int i = 0; i < 8; i++) {
                float xv = xs[r0 + i][k];
                acc[i][0] += xv * w4.x;
                acc[i][1] += xv * w4.y;
                acc[i][2] += xv * w4.z;
                acc[i][3] += xv * w4.w;
            }
        }
        __syncthreads();
    }

    float4 al4 = *(const float4*)&al1[c0];
    float4 ar4 = *(const float4*)&ar1[c0];
    int head = lane >> 3;
#pragma unroll
    for (int i = 0; i < 8; i++) {
        int gr = row0 + r0 + i;
        float elp = acc[i][0]*al4.x + acc[i][1]*al4.y + acc[i][2]*al4.z + acc[i][3]*al4.w;
        float erp = acc[i][0]*ar4.x + acc[i][1]*ar4.y + acc[i][2]*ar4.z + acc[i][3]*ar4.w;
#pragma unroll
        for (int m = 1; m < 8; m <<= 1) {
            elp += __shfl_xor_sync(0xffffffffu, elp, m);
            erp += __shfl_xor_sync(0xffffffffu, erp, m);
        }
        if (gr < n) {
            __half2 h01 = __floats2half2_rn(acc[i][0], acc[i][1]);
            __half2 h23 = __floats2half2_rn(acc[i][2], acc[i][3]);
            uint2 packed = make_uint2(*(unsigned*)&h01, *(unsigned*)&h23);
            *(uint2*)&g_feat1h[(long)gr * HD + c0] = packed;
            if ((lane & 7) == 0) {
                g_el1[gr * 4 + head] = elp;
                g_er1[gr * 4 + head] = erp;
            }
        }
    }
}

// ---------------- K2: fused layer-1, edge loop unrolled x4 --------------
__global__ __launch_bounds__(256) void k_layer1(const float* __restrict__ b1, int n) {
    int wid = (blockIdx.x * blockDim.x + threadIdx.x) >> 5;
    if (wid >= n) return;
    int lane = threadIdx.x & 31;
    int head = lane >> 3;
    long fofs = lane * 4;
    int off0 = g_off[wid], off1 = g_off[wid + 1];
    float er = g_er1[wid * 4 + head];
    float ax = 0.f, ay = 0.f, az = 0.f, aw = 0.f, wsum = 0.f;

    int j = off0;
    for (; j + 4 <= off1; j += 4) {
        int s0 = __ldg(&g_ebuf[j]);
        int s1 = __ldg(&g_ebuf[j + 1]);
        int s2 = __ldg(&g_ebuf[j + 2]);
        int s3 = __ldg(&g_ebuf[j + 3]);
        float e0 = __ldg(&g_el1[s0 * 4 + head]);
        float e1 = __ldg(&g_el1[s1 * 4 + head]);
        float e2 = __ldg(&g_el1[s2 * 4 + head]);
        float e3 = __ldg(&g_el1[s3 * 4 + head]);
        uint2 p0 = *(const uint2*)&g_feat1h[(long)s0 * HD + fofs];
        uint2 p1 = *(const uint2*)&g_feat1h[(long)s1 * HD + fofs];
        uint2 p2 = *(const uint2*)&g_feat1h[(long)s2 * HD + fofs];
        uint2 p3 = *(const uint2*)&g_feat1h[(long)s3 * HD + fofs];
        float w0 = __expf(lrelu(e0 + er));
        float w1 = __expf(lrelu(e1 + er));
        float w2 = __expf(lrelu(e2 + er));
        float w3 = __expf(lrelu(e3 + er));
        wsum += (w0 + w1) + (w2 + w3);
        float2 a0 = __half22float2(*(__half2*)&p0.x), b0 = __half22float2(*(__half2*)&p0.y);
        float2 a1 = __half22float2(*(__half2*)&p1.x), b1v = __half22float2(*(__half2*)&p1.y);
        float2 a2 = __half22float2(*(__half2*)&p2.x), b2v = __half22float2(*(__half2*)&p2.y);
        float2 a3 = __half22float2(*(__half2*)&p3.x), b3v = __half22float2(*(__half2*)&p3.y);
        ax += a0.x * w0 + a1.x * w1 + a2.x * w2 + a3.x * w3;
        ay += a0.y * w0 + a1.y * w1 + a2.y * w2 + a3.y * w3;
        az += b0.x * w0 + b1v.x * w1 + b2v.x * w2 + b3v.x * w3;
        aw += b0.y * w0 + b1v.y * w1 + b2v.y * w2 + b3v.y * w3;
    }
    for (; j < off1; j++) {
        int s = __ldg(&g_ebuf[j]);
        float el = __ldg(&g_el1[s * 4 + head]);
        uint2 p = *(const uint2*)&g_feat1h[(long)s * HD + fofs];
        float w = __expf(lrelu(el + er));
        float2 f01 = __half22float2(*(__half2*)&p.x);
        float2 f23 = __half22float2(*(__half2*)&p.y);
        ax += f01.x * w; ay += f01.y * w; az += f23.x * w; aw += f23.y * w;
        wsum += w;
    }
    float inv = 1.f / fmaxf(wsum, 1e-9f);
    float4 b = *(const float4*)&b1[lane * 4];
    float4 o;
    o.x = elu1(ax * inv + b.x);
    o.y = elu1(ay * inv + b.y);
    o.z = elu1(az * inv + b.z);
    o.w = elu1(aw * inv + b.w);
    *(float4*)&g_h[(long)wid * HD + lane * 4] = o;
}

// ---------------- K3: feat2 = h @ W2 + el2/er2 --------------------------
__global__ __launch_bounds__(256) void k_gemm2(const float* __restrict__ W2,
                                               const float* __restrict__ al2,
                                               const float* __restrict__ ar2, int n) {
    __shared__ float w2s[HD * C];
    __shared__ float al2s[C], ar2s[C];
    int t = threadIdx.x;
    for (int j = t; j < HD * C; j += 256) w2s[j] = W2[j];
    if (t < C) { al2s[t] = al2[t]; ar2s[t] = ar2[t]; }
    __syncthreads();
    int node = blockIdx.x * 256 + t;
    if (node >= n) return;
    float acc[C];
#pragma unroll
    for (int c = 0; c < C; c++) acc[c] = 0.f;
    const float* hr = &g_h[(long)node * HD];
#pragma unroll 4
    for (int kk = 0; kk < 32; kk++) {
        float4 f = *(const float4*)&hr[kk * 4];
        const float* wrow = &w2s[(kk * 4) * C];
#pragma unroll
        for (int c = 0; c < C; c++) {
            acc[c] += f.x * wrow[c] + f.y * wrow[C + c] + f.z * wrow[2 * C + c] + f.w * wrow[3 * C + c];
        }
    }
    float el = 0.f, er = 0.f;
#pragma unroll
    for (int c = 0; c < C; c++) { el += acc[c] * al2s[c]; er += acc[c] * ar2s[c]; }
    __half* outp = &g_feat2h[(long)node * C];
#pragma unroll
    for (int c2 = 0; c2 < 8; c2++) {
        __half2 hv = __floats2half2_rn(acc[c2 * 2], acc[c2 * 2 + 1]);
        *(__half2*)&outp[c2 * 2] = hv;
    }
    g_el2[node] = el;
    g_er2[node] = er;
}

// ---------------- K4: fused layer-2, edge loop unrolled x4 --------------
__global__ __launch_bounds__(256) void k_layer2(const float* __restrict__ b2,
                                                float* __restrict__ out, int n) {
    int t = threadIdx.x;
    int d = blockIdx.x * 16 + (t >> 4);
    if (d >= n) return;
    int c = t & 15;
    int off0 = g_off[d], off1 = g_off[d + 1];
    float er = g_er2[d];
    float acc = 0.f, wsum = 0.f;

    int j = off0;
    for (; j + 4 <= off1; j += 4) {
        int s0 = __ldg(&g_ebuf[j]);
        int s1 = __ldg(&g_ebuf[j + 1]);
        int s2 = __ldg(&g_ebuf[j + 2]);
        int s3 = __ldg(&g_ebuf[j + 3]);
        float e0 = __ldg(&g_el2[s0]);
        float e1 = __ldg(&g_el2[s1]);
        float e2 = __ldg(&g_el2[s2]);
        float e3 = __ldg(&g_el2[s3]);
        float f0 = __half2float(g_feat2h[(long)s0 * C + c]);
        float f1 = __half2float(g_feat2h[(long)s1 * C + c]);
        float f2 = __half2float(g_feat2h[(long)s2 * C + c]);
        float f3 = __half2float(g_feat2h[(long)s3 * C + c]);
        float w0 = __expf(lrelu(e0 + er));
        float w1 = __expf(lrelu(e1 + er));
        float w2 = __expf(lrelu(e2 + er));
        float w3 = __expf(lrelu(e3 + er));
        acc += f0 * w0 + f1 * w1 + f2 * w2 + f3 * w3;
        wsum += (w0 + w1) + (w2 + w3);
    }
    for (; j < off1; j++) {
        int s = __ldg(&g_ebuf[j]);
        float el = __ldg(&g_el2[s]);
        float f = __half2float(g_feat2h[(long)s * C + c]);
        float w = __expf(lrelu(el + er));
        acc += f * w;
        wsum += w;
    }
    out[(long)d * C + c] = acc / fmaxf(wsum, 1e-9f) + __ldg(&b2[c]);
}

extern "C" void kernel_launch(void* const* d_in, const int* in_sizes, int n_in,
                              void* d_out, int out_size) {
    const float* x   = (const float*)d_in[0];
    const int*   src = (const int*)d_in[1];
    const int*   dst = (const int*)d_in[2];
    const float* W1  = (const float*)d_in[3];
    const float* b1  = (const float*)d_in[4];
    const float* al1 = (const float*)d_in[5];
    const float* ar1 = (const float*)d_in[6];
    const float* W2  = (const float*)d_in[7];
    const float* b2  = (const float*)d_in[8];
    const float* al2 = (const float*)d_in[9];
    const float* ar2 = (const float*)d_in[10];
    float* out = (float*)d_out;

    int n = in_sizes[0] / FIN;   // 50000
    int e = in_sizes[1];         // 1600000
    int eb = (e + 255) / 256;

    k_zero_cnt<<<NBLK, 256>>>();
    k_gemm1<<<(n + 63) / 64, 256>>>(x, W1, al1, ar1, n);
    k_hist<<<eb, 256>>>(dst, e);
    k_scan1<<<NBLK, 256>>>();
    k_scan2<<<1, 256>>>();
    k_scan3<<<NBLK, 256>>>(e);
    k_scatter<<<eb, 256>>>(src, dst, e);

    k_layer1<<<(n * 32 + 255) / 256, 256>>>(b1, n);
    k_gemm2<<<(n + 255) / 256, 256>>>(W2, al2, ar2, n);
    k_layer2<<<(n * 16 + 255) / 256, 256>>>(b2, out, n);
}